// round 6
// baseline (speedup 1.0000x reference)
#include <cuda_runtime.h>
#include <cuda_bf16.h>
#include <cstdint>

#define NH 12
#define HD 64
#define CD 768
#define LS 1024
#define BATCH 4
#define ML (BATCH*LS)
#define ATT_SCALE 0.125f

// Pre-split bf16 scratch (hi+lo pairs). [B,H,L,D] for q/k/v, [B,L,C] for o.
__device__ __align__(16) __nv_bfloat16 g_qh[ML*CD], g_ql[ML*CD];
__device__ __align__(16) __nv_bfloat16 g_kh[ML*CD], g_kl[ML*CD];
__device__ __align__(16) __nv_bfloat16 g_vh[ML*CD], g_vl[ML*CD];
__device__ __align__(16) __nv_bfloat16 g_oh[ML*CD], g_ol[ML*CD];

// ---------------- helpers ----------------
__device__ __forceinline__ uint32_t sptr(const void* p) {
    return (uint32_t)__cvta_generic_to_shared(p);
}
__device__ __forceinline__ void bsplit(float x, float y, uint32_t& hp, uint32_t& lp) {
    __nv_bfloat16 hx = __float2bfloat16_rn(x);
    __nv_bfloat16 hy = __float2bfloat16_rn(y);
    float rx = x - __bfloat162float(hx);
    float ry = y - __bfloat162float(hy);
    __nv_bfloat16 lx = __float2bfloat16_rn(rx);
    __nv_bfloat16 ly = __float2bfloat16_rn(ry);
    hp = (uint32_t)__bfloat16_as_ushort(hx) | ((uint32_t)__bfloat16_as_ushort(hy) << 16);
    lp = (uint32_t)__bfloat16_as_ushort(lx) | ((uint32_t)__bfloat16_as_ushort(ly) << 16);
}
__device__ __forceinline__ void ldsm4(uint32_t* r, uint32_t a) {
    asm volatile("ldmatrix.sync.aligned.m8n8.x4.shared.b16 {%0,%1,%2,%3},[%4];\n"
                 : "=r"(r[0]), "=r"(r[1]), "=r"(r[2]), "=r"(r[3]) : "r"(a));
}
__device__ __forceinline__ void ldsm4t(uint32_t* r, uint32_t a) {
    asm volatile("ldmatrix.sync.aligned.m8n8.x4.trans.shared.b16 {%0,%1,%2,%3},[%4];\n"
                 : "=r"(r[0]), "=r"(r[1]), "=r"(r[2]), "=r"(r[3]) : "r"(a));
}
__device__ __forceinline__ void mma_bf16(float* c, const uint32_t* a, uint32_t b0, uint32_t b1) {
    asm volatile(
        "mma.sync.aligned.m16n8k16.row.col.f32.bf16.bf16.f32 "
        "{%0,%1,%2,%3},{%4,%5,%6,%7},{%8,%9},{%0,%1,%2,%3};\n"
        : "+f"(c[0]), "+f"(c[1]), "+f"(c[2]), "+f"(c[3])
        : "r"(a[0]), "r"(a[1]), "r"(a[2]), "r"(a[3]), "r"(b0), "r"(b1));
}
__device__ __forceinline__ void cpa16(uint32_t dst, const void* src) {
    asm volatile("cp.async.cg.shared.global [%0], [%1], 16;\n" :: "r"(dst), "l"(src));
}
__device__ __forceinline__ void cp_commit() { asm volatile("cp.async.commit_group;\n"); }
template<int N> __device__ __forceinline__ void cp_wait() {
    asm volatile("cp.async.wait_group %0;\n" :: "n"(N));
}

// ---------------------------------------------------------------------------
// QKV projection: C[m,n] = sum_k (x[m,k]+ape[l,k]) * W[n,k], bf16x3 MMA.
// Block 128x128, BK=16, 256 thr (8 warps 2x4), warp 64x32.
// Epilogue writes bf16 hi/lo pairs in [B,H,L,D].
// ---------------------------------------------------------------------------
#define AST 24   // smem row stride (bf16) for 16-wide K tiles, LDSM conflict-free

__global__ __launch_bounds__(256) void qkv_kernel(
    const float* __restrict__ x,
    const float* __restrict__ qape,
    const float* __restrict__ kape,
    const float* __restrict__ Wq,
    const float* __restrict__ Wk,
    const float* __restrict__ Wv)
{
    __shared__ __nv_bfloat16 Ah[2][128][AST], Al[2][128][AST];
    __shared__ __nv_bfloat16 Bh[2][128][AST], Bl[2][128][AST];

    const int which = blockIdx.z;
    const float* ape = (which == 0) ? qape : (which == 1) ? kape : nullptr;
    const float* W   = (which == 0) ? Wq   : (which == 1) ? Wk   : Wv;
    __nv_bfloat16* outh = (which == 0) ? g_qh : (which == 1) ? g_kh : g_vh;
    __nv_bfloat16* outl = (which == 0) ? g_ql : (which == 1) ? g_kl : g_vl;

    const int tid  = threadIdx.x;
    const int lane = tid & 31;
    const int warp = tid >> 5;
    const int gid  = lane >> 2;
    const int tig  = lane & 3;
    const int wm   = warp >> 2;
    const int wn   = warp & 3;

    const int m0 = blockIdx.y * 128;
    const int n0 = blockIdx.x * 128;
    const int lr = tid >> 1;
    const int lc = (tid & 1) << 3;

    const float* arow = x + (size_t)(m0 + lr) * CD + lc;
    const float* prow = ape ? ape + (size_t)((m0 + lr) & (LS - 1)) * CD + lc : nullptr;
    const float* brow = W + (size_t)(n0 + lr) * CD + lc;

    float c[4][4][4];
#pragma unroll
    for (int i = 0; i < 4; i++)
#pragma unroll
        for (int j = 0; j < 4; j++)
#pragma unroll
            for (int v = 0; v < 4; v++) c[i][j][v] = 0.f;

    float ar[8], br[8];
    // first tile
    {
        float4 a0 = *(const float4*)(arow);
        float4 a1 = *(const float4*)(arow + 4);
        if (prow) {
            float4 p0 = *(const float4*)(prow);
            float4 p1 = *(const float4*)(prow + 4);
            a0.x += p0.x; a0.y += p0.y; a0.z += p0.z; a0.w += p0.w;
            a1.x += p1.x; a1.y += p1.y; a1.z += p1.z; a1.w += p1.w;
        }
        float4 b0 = *(const float4*)(brow);
        float4 b1 = *(const float4*)(brow + 4);
        ar[0]=a0.x; ar[1]=a0.y; ar[2]=a0.z; ar[3]=a0.w;
        ar[4]=a1.x; ar[5]=a1.y; ar[6]=a1.z; ar[7]=a1.w;
        br[0]=b0.x; br[1]=b0.y; br[2]=b0.z; br[3]=b0.w;
        br[4]=b1.x; br[5]=b1.y; br[6]=b1.z; br[7]=b1.w;
        uint32_t h[4], l[4];
#pragma unroll
        for (int i = 0; i < 4; i++) bsplit(ar[2*i], ar[2*i+1], h[i], l[i]);
        *(uint4*)&Ah[0][lr][lc] = make_uint4(h[0], h[1], h[2], h[3]);
        *(uint4*)&Al[0][lr][lc] = make_uint4(l[0], l[1], l[2], l[3]);
#pragma unroll
        for (int i = 0; i < 4; i++) bsplit(br[2*i], br[2*i+1], h[i], l[i]);
        *(uint4*)&Bh[0][lr][lc] = make_uint4(h[0], h[1], h[2], h[3]);
        *(uint4*)&Bl[0][lr][lc] = make_uint4(l[0], l[1], l[2], l[3]);
    }
    __syncthreads();

    const int arow_s = wm * 64 + (lane & 15);
    const int acol_s = (lane >> 4) * 8;
    const int brow_s = wn * 32 + ((lane >> 4) & 1) * 8 + (lane & 7);
    const int bcol_s = ((lane >> 3) & 1) * 8;

    int st = 0;
    const int NIT = CD / 16;
    for (int it = 0; it < NIT; ++it) {
        if (it + 1 < NIT) {
            int k0 = (it + 1) * 16;
            float4 a0 = *(const float4*)(arow + k0);
            float4 a1 = *(const float4*)(arow + k0 + 4);
            if (prow) {
                float4 p0 = *(const float4*)(prow + k0);
                float4 p1 = *(const float4*)(prow + k0 + 4);
                a0.x += p0.x; a0.y += p0.y; a0.z += p0.z; a0.w += p0.w;
                a1.x += p1.x; a1.y += p1.y; a1.z += p1.z; a1.w += p1.w;
            }
            float4 b0 = *(const float4*)(brow + k0);
            float4 b1 = *(const float4*)(brow + k0 + 4);
            ar[0]=a0.x; ar[1]=a0.y; ar[2]=a0.z; ar[3]=a0.w;
            ar[4]=a1.x; ar[5]=a1.y; ar[6]=a1.z; ar[7]=a1.w;
            br[0]=b0.x; br[1]=b0.y; br[2]=b0.z; br[3]=b0.w;
            br[4]=b1.x; br[5]=b1.y; br[6]=b1.z; br[7]=b1.w;
        }

        uint32_t fah[4][4], fal[4][4], fbh[2][4], fbl[2][4];
#pragma unroll
        for (int ma = 0; ma < 4; ma++) {
            ldsm4(fah[ma], sptr(&Ah[st][arow_s + ma * 16][acol_s]));
            ldsm4(fal[ma], sptr(&Al[st][arow_s + ma * 16][acol_s]));
        }
#pragma unroll
        for (int np = 0; np < 2; np++) {
            ldsm4(fbh[np], sptr(&Bh[st][brow_s + np * 16][bcol_s]));
            ldsm4(fbl[np], sptr(&Bl[st][brow_s + np * 16][bcol_s]));
        }
#pragma unroll
        for (int ma = 0; ma < 4; ma++)
#pragma unroll
            for (int nb = 0; nb < 4; nb++) {
                const int np = nb >> 1, sel = (nb & 1) * 2;
                mma_bf16(c[ma][nb], fah[ma], fbh[np][sel], fbh[np][sel + 1]);
                mma_bf16(c[ma][nb], fah[ma], fbl[np][sel], fbl[np][sel + 1]);
                mma_bf16(c[ma][nb], fal[ma], fbh[np][sel], fbh[np][sel + 1]);
            }

        if (it + 1 < NIT) {
            uint32_t h[4], l[4];
#pragma unroll
            for (int i = 0; i < 4; i++) bsplit(ar[2*i], ar[2*i+1], h[i], l[i]);
            *(uint4*)&Ah[st ^ 1][lr][lc] = make_uint4(h[0], h[1], h[2], h[3]);
            *(uint4*)&Al[st ^ 1][lr][lc] = make_uint4(l[0], l[1], l[2], l[3]);
#pragma unroll
            for (int i = 0; i < 4; i++) bsplit(br[2*i], br[2*i+1], h[i], l[i]);
            *(uint4*)&Bh[st ^ 1][lr][lc] = make_uint4(h[0], h[1], h[2], h[3]);
            *(uint4*)&Bl[st ^ 1][lr][lc] = make_uint4(l[0], l[1], l[2], l[3]);
            __syncthreads();
            st ^= 1;
        }
    }

    // epilogue -> [B,H,L,D] bf16 hi/lo pairs
#pragma unroll
    for (int ma = 0; ma < 4; ma++) {
        int row0 = m0 + wm * 64 + ma * 16 + gid;
        int row1 = row0 + 8;
        int b0i = row0 >> 10, l0 = row0 & (LS - 1);
        int b1i = row1 >> 10, l1 = row1 & (LS - 1);
#pragma unroll
        for (int nb = 0; nb < 4; nb++) {
            int n = n0 + wn * 32 + nb * 8 + 2 * tig;
            int h = n >> 6, d = n & 63;
            size_t o0 = ((size_t)((b0i * NH + h) * LS + l0)) * HD + d;
            size_t o1 = ((size_t)((b1i * NH + h) * LS + l1)) * HD + d;
            uint32_t hp, lp;
            bsplit(c[ma][nb][0], c[ma][nb][1], hp, lp);
            *(uint32_t*)(outh + o0) = hp;
            *(uint32_t*)(outl + o0) = lp;
            bsplit(c[ma][nb][2], c[ma][nb][3], hp, lp);
            *(uint32_t*)(outh + o1) = hp;
            *(uint32_t*)(outl + o1) = lp;
        }
    }
}

// ---------------------------------------------------------------------------
// Attention: per (b,h), 64-query block, 4 warps x 16 q-rows, 32-key tiles.
// All operands pre-split bf16 via cp.async, double-buffered. bf16x3 MMAs.
// ---------------------------------------------------------------------------
#define KST 72   // smem row stride (bf16) for 64-wide tiles

__global__ __launch_bounds__(128) void attn_kernel(const float* __restrict__ pos)
{
    // [stage][{Kh,Kl,Vh,Vl}][row][col]; stage0 doubles as Q staging in prologue
    __shared__ __nv_bfloat16 S[2][4][32][KST];

    const int tid  = threadIdx.x;
    const int lane = tid & 31;
    const int warp = tid >> 5;
    const int gid  = lane >> 2;
    const int tig  = lane & 3;

    const int bh = blockIdx.y;
    const int b  = bh / NH;
    const int h  = bh - b * NH;
    const int q0 = blockIdx.x * 64;

    const size_t base = (size_t)bh * LS * HD;

    // ---- prologue: Q into stage-0 region, build register fragments ----
    __nv_bfloat16* Qh = &S[0][0][0][0];          // [64][KST]
    __nv_bfloat16* Ql = Qh + 64 * KST;
    {
        // warp 0: Qh rows 0-31, warp 1: Qh 32-63, warp 2: Ql 0-31, warp 3: Ql 32-63
        const __nv_bfloat16* src = ((warp & 2) ? g_ql : g_qh) +
            base + (size_t)(q0 + (warp & 1) * 32 + lane) * HD;
        __nv_bfloat16* dst = ((warp & 2) ? Ql : Qh) + ((warp & 1) * 32 + lane) * KST;
        uint32_t d0 = sptr(dst);
#pragma unroll
        for (int cidx = 0; cidx < 8; cidx++) cpa16(d0 + cidx * 16, src + cidx * 8);
    }
    cp_commit();
    cp_wait<0>();
    __syncthreads();

    uint32_t qfh[4][4], qfl[4][4];
    {
        const int qrow = warp * 16 + (lane & 15);
        const int qc   = (lane >> 4) * 8;
#pragma unroll
        for (int kc = 0; kc < 4; kc++) {
            ldsm4(qfh[kc], sptr(Qh + qrow * KST + kc * 16 + qc));
            ldsm4(qfl[kc], sptr(Ql + qrow * KST + kc * 16 + qc));
        }
    }
    __syncthreads();   // Q region free -> becomes KV stage 0

    // KV loader: warp w loads array w (Kh,Kl,Vh,Vl), row = lane
    const __nv_bfloat16* kvsrc =
        ((warp == 0) ? g_kh : (warp == 1) ? g_kl : (warp == 2) ? g_vh : g_vl) + base;

    {   // stage 0, j0 = 0
        const __nv_bfloat16* src = kvsrc + (size_t)lane * HD;
        uint32_t d0 = sptr(&S[0][warp][lane][0]);
#pragma unroll
        for (int cidx = 0; cidx < 8; cidx++) cpa16(d0 + cidx * 16, src + cidx * 8);
    }
    cp_commit();

    const int r = warp * 16 + gid;
    float o[8][4];
#pragma unroll
    for (int nd = 0; nd < 8; nd++)
#pragma unroll
        for (int v = 0; v < 4; v++) o[nd][v] = 0.f;
    float mi[2] = {-1e30f, -1e30f};
    float li[2] = {0.f, 0.f};

    const int krow_s = ((lane >> 4) & 1) * 8 + (lane & 7);   // within 16-row group
    const int kcol_s = ((lane >> 3) & 1) * 8;
    const int vrow_s = ((lane >> 3) & 1) * 8 + (lane & 7);
    const int vcol_s = ((lane >> 4) & 1) * 8;

    const int NJ = LS / 32;
    for (int i = 0; i < NJ; i++) {
        const int st = i & 1;
        if (i + 1 < NJ) {
            const __nv_bfloat16* src = kvsrc + (size_t)((i + 1) * 32 + lane) * HD;
            uint32_t d0 = sptr(&S[st ^ 1][warp][lane][0]);
#pragma unroll
            for (int cidx = 0; cidx < 8; cidx++) cpa16(d0 + cidx * 16, src + cidx * 8);
            cp_commit();
            cp_wait<1>();
        } else {
            cp_wait<0>();
        }
        __syncthreads();

        // ---- S = Q K^T ----
        float s[4][4];
#pragma unroll
        for (int nb = 0; nb < 4; nb++)
#pragma unroll
            for (int v = 0; v < 4; v++) s[nb][v] = 0.f;

#pragma unroll
        for (int kc = 0; kc < 4; kc++)
#pragma unroll
            for (int np = 0; np < 2; np++) {
                uint32_t kh[4], kl[4];
                ldsm4(kh, sptr(&S[st][0][np * 16 + krow_s][kc * 16 + kcol_s]));
                ldsm4(kl, sptr(&S[st][1][np * 16 + krow_s][kc * 16 + kcol_s]));
                mma_bf16(s[2*np],   qfh[kc], kh[0], kh[1]);
                mma_bf16(s[2*np],   qfh[kc], kl[0], kl[1]);
                mma_bf16(s[2*np],   qfl[kc], kh[0], kh[1]);
                mma_bf16(s[2*np+1], qfh[kc], kh[2], kh[3]);
                mma_bf16(s[2*np+1], qfh[kc], kl[2], kl[3]);
                mma_bf16(s[2*np+1], qfl[kc], kh[2], kh[3]);
            }

        // ---- scale + pos + online softmax ----
        const int j0 = i * 32;
#pragma unroll
        for (int rp = 0; rp < 2; rp++) {
            int row = r + rp * 8;
            const float* pb = pos + ((size_t)(h * LS + q0 + row)) * LS + j0 + 2 * tig;
            float rm = -1e30f;
#pragma unroll
            for (int nb = 0; nb < 4; nb++) {
                float2 pv = *(const float2*)(pb + nb * 8);
                float v0 = fmaf(s[nb][2*rp],     ATT_SCALE, pv.x);
                float v1 = fmaf(s[nb][2*rp + 1], ATT_SCALE, pv.y);
                s[nb][2*rp]     = v0;
                s[nb][2*rp + 1] = v1;
                rm = fmaxf(rm, fmaxf(v0, v1));
            }
            rm = fmaxf(rm, __shfl_xor_sync(0xffffffffu, rm, 1));
            rm = fmaxf(rm, __shfl_xor_sync(0xffffffffu, rm, 2));
            float mnew  = fmaxf(mi[rp], rm);
            float alpha = __expf(mi[rp] - mnew);
            mi[rp] = mnew;
            float rs = 0.f;
#pragma unroll
            for (int nb = 0; nb < 4; nb++) {
                float e0 = __expf(s[nb][2*rp]     - mnew);
                float e1 = __expf(s[nb][2*rp + 1] - mnew);
                s[nb][2*rp]     = e0;
                s[nb][2*rp + 1] = e1;
                rs += e0 + e1;
            }
            rs += __shfl_xor_sync(0xffffffffu, rs, 1);
            rs += __shfl_xor_sync(0xffffffffu, rs, 2);
            li[rp] = li[rp] * alpha + rs;
#pragma unroll
            for (int nd = 0; nd < 8; nd++) {
                o[nd][2*rp]     *= alpha;
                o[nd][2*rp + 1] *= alpha;
            }
        }

        // ---- P fragments (split bf16, register-only) ----
        uint32_t ph[2][4], pl[2][4];
#pragma unroll
        for (int kc = 0; kc < 2; kc++) {
            bsplit(s[2*kc][0],   s[2*kc][1],   ph[kc][0], pl[kc][0]);
            bsplit(s[2*kc][2],   s[2*kc][3],   ph[kc][1], pl[kc][1]);
            bsplit(s[2*kc+1][0], s[2*kc+1][1], ph[kc][2], pl[kc][2]);
            bsplit(s[2*kc+1][2], s[2*kc+1][3], ph[kc][3], pl[kc][3]);
        }

        // ---- O += P V ----
#pragma unroll
        for (int kc = 0; kc < 2; kc++)
#pragma unroll
            for (int np = 0; np < 4; np++) {
                uint32_t vh[4], vl[4];
                ldsm4t(vh, sptr(&S[st][2][kc * 16 + vrow_s][np * 16 + vcol_s]));
                ldsm4t(vl, sptr(&S[st][3][kc * 16 + vrow_s][np * 16 + vcol_s]));
                mma_bf16(o[2*np],   ph[kc], vh[0], vh[1]);
                mma_bf16(o[2*np],   ph[kc], vl[0], vl[1]);
                mma_bf16(o[2*np],   pl[kc], vh[0], vh[1]);
                mma_bf16(o[2*np+1], ph[kc], vh[2], vh[3]);
                mma_bf16(o[2*np+1], ph[kc], vl[2], vl[3]);
                mma_bf16(o[2*np+1], pl[kc], vh[2], vh[3]);
            }

        __syncthreads();
    }

    // ---- epilogue: normalize, write bf16 hi/lo [B,L,C] ----
    float inv0 = 1.0f / li[0];
    float inv1 = 1.0f / li[1];
#pragma unroll
    for (int nd = 0; nd < 8; nd++) {
        int d = nd * 8 + 2 * tig;
        size_t o0 = ((size_t)(b * LS + q0 + r)) * CD + h * HD + d;
        size_t o1 = ((size_t)(b * LS + q0 + r + 8)) * CD + h * HD + d;
        uint32_t hp, lp;
        bsplit(o[nd][0] * inv0, o[nd][1] * inv0, hp, lp);
        *(uint32_t*)(g_oh + o0) = hp;
        *(uint32_t*)(g_ol + o0) = lp;
        bsplit(o[nd][2] * inv1, o[nd][3] * inv1, hp, lp);
        *(uint32_t*)(g_oh + o1) = hp;
        *(uint32_t*)(g_ol + o1) = lp;
    }
}

// ---------------------------------------------------------------------------
// Output projection: out = g_o @ Wp^T + bp. A pre-split bf16, B split in-kernel.
// ---------------------------------------------------------------------------
__global__ __launch_bounds__(256) void proj_kernel(
    const float* __restrict__ Wp,
    const float* __restrict__ bp,
    float* __restrict__ out)
{
    __shared__ __nv_bfloat16 Ah[2][128][AST], Al[2][128][AST];
    __shared__ __nv_bfloat16 Bh[2][128][AST], Bl[2][128][AST];

    const int tid  = threadIdx.x;
    const int lane = tid & 31;
    const int warp = tid >> 5;
    const int gid  = lane >> 2;
    const int tig  = lane & 3;
    const int wm   = warp >> 2;
    const int wn   = warp & 3;

    const int m0 = blockIdx.y * 128;
    const int n0 = blockIdx.x * 128;
    const int lr = tid >> 1;
    const int lc = (tid & 1) << 3;

    const __nv_bfloat16* ahrow = g_oh + (size_t)(m0 + lr) * CD + lc;
    const __nv_bfloat16* alrow = g_ol + (size_t)(m0 + lr) * CD + lc;
    const float* brow = Wp + (size_t)(n0 + lr) * CD + lc;

    float c[4][4][4];
#pragma unroll
    for (int i = 0; i < 4; i++)
#pragma unroll
        for (int j = 0; j < 4; j++)
#pragma unroll
            for (int v = 0; v < 4; v++) c[i][j][v] = 0.f;

    uint4 pa_h, pa_l;
    float br[8];
    {
        pa_h = *(const uint4*)ahrow;
        pa_l = *(const uint4*)alrow;
        float4 b0 = *(const float4*)(brow);
        float4 b1 = *(const float4*)(brow + 4);
        br[0]=b0.x; br[1]=b0.y; br[2]=b0.z; br[3]=b0.w;
        br[4]=b1.x; br[5]=b1.y; br[6]=b1.z; br[7]=b1.w;
        *(uint4*)&Ah[0][lr][lc] = pa_h;
        *(uint4*)&Al[0][lr][lc] = pa_l;
        uint32_t h[4], l[4];
#pragma unroll
        for (int i = 0; i < 4; i++) bsplit(br[2*i], br[2*i+1], h[i], l[i]);
        *(uint4*)&Bh[0][lr][lc] = make_uint4(h[0], h[1], h[2], h[3]);
        *(uint4*)&Bl[0][lr][lc] = make_uint4(l[0], l[1], l[2], l[3]);
    }
    __syncthreads();

    const int arow_s = wm * 64 + (lane & 15);
    const int acol_s = (lane >> 4) * 8;
    const int brow_s = wn * 32 + ((lane >> 4) & 1) * 8 + (lane & 7);
    const int bcol_s = ((lane >> 3) & 1) * 8;

    int st = 0;
    const int NIT = CD / 16;
    for (int it = 0; it < NIT; ++it) {
        if (it + 1 < NIT) {
            int k0 = (it + 1) * 16;
            pa_h = *(const uint4*)(ahrow + k0);
            pa_l = *(const uint4*)(alrow + k0);
            float4 b0 = *(const float4*)(brow + k0);
            float4 b1 = *(const float4*)(brow + k0 + 4);
            br[0]=b0.x; br[1]=b0.y; br[2]=b0.z; br[3]=b0.w;
            br[4]=b1.x; br[5]=b1.y; br[6]=b1.z; br[7]=b1.w;
        }

        uint32_t fah[4][4], fal[4][4], fbh[2][4], fbl[2][4];
#pragma unroll
        for (int ma = 0; ma < 4; ma++) {
            ldsm4(fah[ma], sptr(&Ah[st][arow_s + ma * 16][acol_s]));
            ldsm4(fal[ma], sptr(&Al[st][arow_s + ma * 16][acol_s]));
        }
#pragma unroll
        for (int np = 0; np < 2; np++) {
            ldsm4(fbh[np], sptr(&Bh[st][brow_s + np * 16][bcol_s]));
            ldsm4(fbl[np], sptr(&Bl[st][brow_s + np * 16][bcol_s]));
        }
#pragma unroll
        for (int ma = 0; ma < 4; ma++)
#pragma unroll
            for (int nb = 0; nb < 4; nb++) {
                const int np = nb >> 1, sel = (nb & 1) * 2;
                mma_bf16(c[ma][nb], fah[ma], fbh[np][sel], fbh[np][sel + 1]);
                mma_bf16(c[ma][nb], fah[ma], fbl[np][sel], fbl[np][sel + 1]);
                mma_bf16(c[ma][nb], fal[ma], fbh[np][sel], fbh[np][sel + 1]);
            }

        if (it + 1 < NIT) {
            *(uint4*)&Ah[st ^ 1][lr][lc] = pa_h;
            *(uint4*)&Al[st ^ 1][lr][lc] = pa_l;
            uint32_t h[4], l[4];
#pragma unroll
            for (int i = 0; i < 4; i++) bsplit(br[2*i], br[2*i+1], h[i], l[i]);
            *(uint4*)&Bh[st ^ 1][lr][lc] = make_uint4(h[0], h[1], h[2], h[3]);
            *(uint4*)&Bl[st ^ 1][lr][lc] = make_uint4(l[0], l[1], l[2], l[3]);
            __syncthreads();
            st ^= 1;
        }
    }

#pragma unroll
    for (int ma = 0; ma < 4; ma++) {
        int row0 = m0 + wm * 64 + ma * 16 + gid;
        int row1 = row0 + 8;
#pragma unroll
        for (int nb = 0; nb < 4; nb++) {
            int n = n0 + wn * 32 + nb * 8 + 2 * tig;
            float2 bias = *(const float2*)(bp + n);
            *(float2*)(out + (size_t)row0 * CD + n) =
                make_float2(c[ma][nb][0] + bias.x, c[ma][nb][1] + bias.y);
            *(float2*)(out + (size_t)row1 * CD + n) =
                make_float2(c[ma][nb][2] + bias.x, c[ma][nb][3] + bias.y);
        }
    }
}

// ---------------------------------------------------------------------------
extern "C" void kernel_launch(void* const* d_in, const int* in_sizes, int n_in,
                              void* d_out, int out_size)
{
    const float* x    = (const float*)d_in[0];
    const float* qape = (const float*)d_in[1];
    const float* kape = (const float*)d_in[2];
    const float* pos  = (const float*)d_in[3];
    const float* Wq   = (const float*)d_in[4];
    const float* Wk   = (const float*)d_in[5];
    const float* Wv   = (const float*)d_in[6];
    const float* Wp   = (const float*)d_in[7];
    const float* bp   = (const float*)d_in[8];
    float* out = (float*)d_out;

    dim3 gemm_grid(CD / 128, ML / 128, 3);
    qkv_kernel<<<gemm_grid, 256>>>(x, qape, kape, Wq, Wk, Wv);

    dim3 attn_grid(LS / 64, BATCH * NH);
    attn_kernel<<<attn_grid, 128>>>(pos);

    dim3 proj_grid(CD / 128, ML / 128, 1);
    proj_kernel<<<proj_grid, 256>>>(Wp, bp, out);
}

// round 7
// speedup vs baseline: 1.0025x; 1.0025x over previous
#include <cuda_runtime.h>
#include <cuda_bf16.h>
#include <cstdint>

#define NH 12
#define HD 64
#define CD 768
#define LS 1024
#define BATCH 4
#define ML (BATCH*LS)
#define ATT_SCALE 0.125f

// Pre-split bf16 scratch (hi+lo pairs). [B,H,L,D] for q/k/v, [B,L,C] for o.
__device__ __align__(16) __nv_bfloat16 g_qh[ML*CD], g_ql[ML*CD];
__device__ __align__(16) __nv_bfloat16 g_kh[ML*CD], g_kl[ML*CD];
__device__ __align__(16) __nv_bfloat16 g_vh[ML*CD], g_vl[ML*CD];
__device__ __align__(16) __nv_bfloat16 g_oh[ML*CD], g_ol[ML*CD];

// ---------------- helpers ----------------
__device__ __forceinline__ uint32_t sptr(const void* p) {
    return (uint32_t)__cvta_generic_to_shared(p);
}
__device__ __forceinline__ void bsplit(float x, float y, uint32_t& hp, uint32_t& lp) {
    __nv_bfloat16 hx = __float2bfloat16_rn(x);
    __nv_bfloat16 hy = __float2bfloat16_rn(y);
    float rx = x - __bfloat162float(hx);
    float ry = y - __bfloat162float(hy);
    __nv_bfloat16 lx = __float2bfloat16_rn(rx);
    __nv_bfloat16 ly = __float2bfloat16_rn(ry);
    hp = (uint32_t)__bfloat16_as_ushort(hx) | ((uint32_t)__bfloat16_as_ushort(hy) << 16);
    lp = (uint32_t)__bfloat16_as_ushort(lx) | ((uint32_t)__bfloat16_as_ushort(ly) << 16);
}
__device__ __forceinline__ void ldsm4(uint32_t* r, uint32_t a) {
    asm volatile("ldmatrix.sync.aligned.m8n8.x4.shared.b16 {%0,%1,%2,%3},[%4];\n"
                 : "=r"(r[0]), "=r"(r[1]), "=r"(r[2]), "=r"(r[3]) : "r"(a));
}
__device__ __forceinline__ void ldsm4t(uint32_t* r, uint32_t a) {
    asm volatile("ldmatrix.sync.aligned.m8n8.x4.trans.shared.b16 {%0,%1,%2,%3},[%4];\n"
                 : "=r"(r[0]), "=r"(r[1]), "=r"(r[2]), "=r"(r[3]) : "r"(a));
}
__device__ __forceinline__ void mma_bf16(float* c, const uint32_t* a, uint32_t b0, uint32_t b1) {
    asm volatile(
        "mma.sync.aligned.m16n8k16.row.col.f32.bf16.bf16.f32 "
        "{%0,%1,%2,%3},{%4,%5,%6,%7},{%8,%9},{%0,%1,%2,%3};\n"
        : "+f"(c[0]), "+f"(c[1]), "+f"(c[2]), "+f"(c[3])
        : "r"(a[0]), "r"(a[1]), "r"(a[2]), "r"(a[3]), "r"(b0), "r"(b1));
}
__device__ __forceinline__ void cpa16(uint32_t dst, const void* src) {
    asm volatile("cp.async.cg.shared.global [%0], [%1], 16;\n" :: "r"(dst), "l"(src));
}
__device__ __forceinline__ void cp_commit() { asm volatile("cp.async.commit_group;\n"); }
template<int N> __device__ __forceinline__ void cp_wait() {
    asm volatile("cp.async.wait_group %0;\n" :: "n"(N));
}

// ---------------------------------------------------------------------------
// QKV projection: C[m,n] = sum_k (x[m,k]+ape[l,k]) * W[n,k], bf16x3 MMA.
// Block 128x128, BK=16, 256 thr (8 warps 2x4), warp 64x32.
// Epilogue writes bf16 hi/lo pairs in [B,H,L,D].
// ---------------------------------------------------------------------------
#define AST 24   // smem row stride (bf16) for 16-wide K tiles, LDSM conflict-free

__global__ __launch_bounds__(256) void qkv_kernel(
    const float* __restrict__ x,
    const float* __restrict__ qape,
    const float* __restrict__ kape,
    const float* __restrict__ Wq,
    const float* __restrict__ Wk,
    const float* __restrict__ Wv)
{
    __shared__ __nv_bfloat16 Ah[2][128][AST], Al[2][128][AST];
    __shared__ __nv_bfloat16 Bh[2][128][AST], Bl[2][128][AST];

    const int which = blockIdx.z;
    const float* ape = (which == 0) ? qape : (which == 1) ? kape : nullptr;
    const float* W   = (which == 0) ? Wq   : (which == 1) ? Wk   : Wv;
    __nv_bfloat16* outh = (which == 0) ? g_qh : (which == 1) ? g_kh : g_vh;
    __nv_bfloat16* outl = (which == 0) ? g_ql : (which == 1) ? g_kl : g_vl;

    const int tid  = threadIdx.x;
    const int lane = tid & 31;
    const int warp = tid >> 5;
    const int gid  = lane >> 2;
    const int tig  = lane & 3;
    const int wm   = warp >> 2;
    const int wn   = warp & 3;

    const int m0 = blockIdx.y * 128;
    const int n0 = blockIdx.x * 128;
    const int lr = tid >> 1;
    const int lc = (tid & 1) << 3;

    const float* arow = x + (size_t)(m0 + lr) * CD + lc;
    const float* prow = ape ? ape + (size_t)((m0 + lr) & (LS - 1)) * CD + lc : nullptr;
    const float* brow = W + (size_t)(n0 + lr) * CD + lc;

    float c[4][4][4];
#pragma unroll
    for (int i = 0; i < 4; i++)
#pragma unroll
        for (int j = 0; j < 4; j++)
#pragma unroll
            for (int v = 0; v < 4; v++) c[i][j][v] = 0.f;

    float ar[8], br[8];
    // first tile
    {
        float4 a0 = *(const float4*)(arow);
        float4 a1 = *(const float4*)(arow + 4);
        if (prow) {
            float4 p0 = *(const float4*)(prow);
            float4 p1 = *(const float4*)(prow + 4);
            a0.x += p0.x; a0.y += p0.y; a0.z += p0.z; a0.w += p0.w;
            a1.x += p1.x; a1.y += p1.y; a1.z += p1.z; a1.w += p1.w;
        }
        float4 b0 = *(const float4*)(brow);
        float4 b1 = *(const float4*)(brow + 4);
        ar[0]=a0.x; ar[1]=a0.y; ar[2]=a0.z; ar[3]=a0.w;
        ar[4]=a1.x; ar[5]=a1.y; ar[6]=a1.z; ar[7]=a1.w;
        br[0]=b0.x; br[1]=b0.y; br[2]=b0.z; br[3]=b0.w;
        br[4]=b1.x; br[5]=b1.y; br[6]=b1.z; br[7]=b1.w;
        uint32_t h[4], l[4];
#pragma unroll
        for (int i = 0; i < 4; i++) bsplit(ar[2*i], ar[2*i+1], h[i], l[i]);
        *(uint4*)&Ah[0][lr][lc] = make_uint4(h[0], h[1], h[2], h[3]);
        *(uint4*)&Al[0][lr][lc] = make_uint4(l[0], l[1], l[2], l[3]);
#pragma unroll
        for (int i = 0; i < 4; i++) bsplit(br[2*i], br[2*i+1], h[i], l[i]);
        *(uint4*)&Bh[0][lr][lc] = make_uint4(h[0], h[1], h[2], h[3]);
        *(uint4*)&Bl[0][lr][lc] = make_uint4(l[0], l[1], l[2], l[3]);
    }
    __syncthreads();

    const int arow_s = wm * 64 + (lane & 15);
    const int acol_s = (lane >> 4) * 8;
    const int brow_s = wn * 32 + ((lane >> 4) & 1) * 8 + (lane & 7);
    const int bcol_s = ((lane >> 3) & 1) * 8;

    int st = 0;
    const int NIT = CD / 16;
    for (int it = 0; it < NIT; ++it) {
        if (it + 1 < NIT) {
            int k0 = (it + 1) * 16;
            float4 a0 = *(const float4*)(arow + k0);
            float4 a1 = *(const float4*)(arow + k0 + 4);
            if (prow) {
                float4 p0 = *(const float4*)(prow + k0);
                float4 p1 = *(const float4*)(prow + k0 + 4);
                a0.x += p0.x; a0.y += p0.y; a0.z += p0.z; a0.w += p0.w;
                a1.x += p1.x; a1.y += p1.y; a1.z += p1.z; a1.w += p1.w;
            }
            float4 b0 = *(const float4*)(brow + k0);
            float4 b1 = *(const float4*)(brow + k0 + 4);
            ar[0]=a0.x; ar[1]=a0.y; ar[2]=a0.z; ar[3]=a0.w;
            ar[4]=a1.x; ar[5]=a1.y; ar[6]=a1.z; ar[7]=a1.w;
            br[0]=b0.x; br[1]=b0.y; br[2]=b0.z; br[3]=b0.w;
            br[4]=b1.x; br[5]=b1.y; br[6]=b1.z; br[7]=b1.w;
        }

        uint32_t fah[4][4], fal[4][4], fbh[2][4], fbl[2][4];
#pragma unroll
        for (int ma = 0; ma < 4; ma++) {
            ldsm4(fah[ma], sptr(&Ah[st][arow_s + ma * 16][acol_s]));
            ldsm4(fal[ma], sptr(&Al[st][arow_s + ma * 16][acol_s]));
        }
#pragma unroll
        for (int np = 0; np < 2; np++) {
            ldsm4(fbh[np], sptr(&Bh[st][brow_s + np * 16][bcol_s]));
            ldsm4(fbl[np], sptr(&Bl[st][brow_s + np * 16][bcol_s]));
        }
#pragma unroll
        for (int ma = 0; ma < 4; ma++)
#pragma unroll
            for (int nb = 0; nb < 4; nb++) {
                const int np = nb >> 1, sel = (nb & 1) * 2;
                mma_bf16(c[ma][nb], fah[ma], fbh[np][sel], fbh[np][sel + 1]);
                mma_bf16(c[ma][nb], fah[ma], fbl[np][sel], fbl[np][sel + 1]);
                mma_bf16(c[ma][nb], fal[ma], fbh[np][sel], fbh[np][sel + 1]);
            }

        if (it + 1 < NIT) {
            uint32_t h[4], l[4];
#pragma unroll
            for (int i = 0; i < 4; i++) bsplit(ar[2*i], ar[2*i+1], h[i], l[i]);
            *(uint4*)&Ah[st ^ 1][lr][lc] = make_uint4(h[0], h[1], h[2], h[3]);
            *(uint4*)&Al[st ^ 1][lr][lc] = make_uint4(l[0], l[1], l[2], l[3]);
#pragma unroll
            for (int i = 0; i < 4; i++) bsplit(br[2*i], br[2*i+1], h[i], l[i]);
            *(uint4*)&Bh[st ^ 1][lr][lc] = make_uint4(h[0], h[1], h[2], h[3]);
            *(uint4*)&Bl[st ^ 1][lr][lc] = make_uint4(l[0], l[1], l[2], l[3]);
            __syncthreads();
            st ^= 1;
        }
    }

    // epilogue -> [B,H,L,D] bf16 hi/lo pairs
#pragma unroll
    for (int ma = 0; ma < 4; ma++) {
        int row0 = m0 + wm * 64 + ma * 16 + gid;
        int row1 = row0 + 8;
        int b0i = row0 >> 10, l0 = row0 & (LS - 1);
        int b1i = row1 >> 10, l1 = row1 & (LS - 1);
#pragma unroll
        for (int nb = 0; nb < 4; nb++) {
            int n = n0 + wn * 32 + nb * 8 + 2 * tig;
            int h = n >> 6, d = n & 63;
            size_t o0 = ((size_t)((b0i * NH + h) * LS + l0)) * HD + d;
            size_t o1 = ((size_t)((b1i * NH + h) * LS + l1)) * HD + d;
            uint32_t hp, lp;
            bsplit(c[ma][nb][0], c[ma][nb][1], hp, lp);
            *(uint32_t*)(outh + o0) = hp;
            *(uint32_t*)(outl + o0) = lp;
            bsplit(c[ma][nb][2], c[ma][nb][3], hp, lp);
            *(uint32_t*)(outh + o1) = hp;
            *(uint32_t*)(outl + o1) = lp;
        }
    }
}

// ---------------------------------------------------------------------------
// Attention: per (b,h), 64-query block, 4 warps x 16 q-rows, 32-key tiles.
// All operands pre-split bf16 via cp.async, double-buffered. bf16x3 MMAs.
// ---------------------------------------------------------------------------
#define KST 72   // smem row stride (bf16) for 64-wide tiles

__global__ __launch_bounds__(128) void attn_kernel(const float* __restrict__ pos)
{
    // [stage][{Kh,Kl,Vh,Vl}][row][col]; stage0 doubles as Q staging in prologue
    __shared__ __nv_bfloat16 S[2][4][32][KST];

    const int tid  = threadIdx.x;
    const int lane = tid & 31;
    const int warp = tid >> 5;
    const int gid  = lane >> 2;
    const int tig  = lane & 3;

    const int bh = blockIdx.y;
    const int b  = bh / NH;
    const int h  = bh - b * NH;
    const int q0 = blockIdx.x * 64;

    const size_t base = (size_t)bh * LS * HD;

    // ---- prologue: Q into stage-0 region, build register fragments ----
    __nv_bfloat16* Qh = &S[0][0][0][0];          // [64][KST]
    __nv_bfloat16* Ql = Qh + 64 * KST;
    {
        // warp 0: Qh rows 0-31, warp 1: Qh 32-63, warp 2: Ql 0-31, warp 3: Ql 32-63
        const __nv_bfloat16* src = ((warp & 2) ? g_ql : g_qh) +
            base + (size_t)(q0 + (warp & 1) * 32 + lane) * HD;
        __nv_bfloat16* dst = ((warp & 2) ? Ql : Qh) + ((warp & 1) * 32 + lane) * KST;
        uint32_t d0 = sptr(dst);
#pragma unroll
        for (int cidx = 0; cidx < 8; cidx++) cpa16(d0 + cidx * 16, src + cidx * 8);
    }
    cp_commit();
    cp_wait<0>();
    __syncthreads();

    uint32_t qfh[4][4], qfl[4][4];
    {
        const int qrow = warp * 16 + (lane & 15);
        const int qc   = (lane >> 4) * 8;
#pragma unroll
        for (int kc = 0; kc < 4; kc++) {
            ldsm4(qfh[kc], sptr(Qh + qrow * KST + kc * 16 + qc));
            ldsm4(qfl[kc], sptr(Ql + qrow * KST + kc * 16 + qc));
        }
    }
    __syncthreads();   // Q region free -> becomes KV stage 0

    // KV loader: warp w loads array w (Kh,Kl,Vh,Vl), row = lane
    const __nv_bfloat16* kvsrc =
        ((warp == 0) ? g_kh : (warp == 1) ? g_kl : (warp == 2) ? g_vh : g_vl) + base;

    {   // stage 0, j0 = 0
        const __nv_bfloat16* src = kvsrc + (size_t)lane * HD;
        uint32_t d0 = sptr(&S[0][warp][lane][0]);
#pragma unroll
        for (int cidx = 0; cidx < 8; cidx++) cpa16(d0 + cidx * 16, src + cidx * 8);
    }
    cp_commit();

    const int r = warp * 16 + gid;
    float o[8][4];
#pragma unroll
    for (int nd = 0; nd < 8; nd++)
#pragma unroll
        for (int v = 0; v < 4; v++) o[nd][v] = 0.f;
    float mi[2] = {-1e30f, -1e30f};
    float li[2] = {0.f, 0.f};

    const int krow_s = ((lane >> 4) & 1) * 8 + (lane & 7);   // within 16-row group
    const int kcol_s = ((lane >> 3) & 1) * 8;
    const int vrow_s = ((lane >> 3) & 1) * 8 + (lane & 7);
    const int vcol_s = ((lane >> 4) & 1) * 8;

    const int NJ = LS / 32;
    for (int i = 0; i < NJ; i++) {
        const int st = i & 1;
        if (i + 1 < NJ) {
            const __nv_bfloat16* src = kvsrc + (size_t)((i + 1) * 32 + lane) * HD;
            uint32_t d0 = sptr(&S[st ^ 1][warp][lane][0]);
#pragma unroll
            for (int cidx = 0; cidx < 8; cidx++) cpa16(d0 + cidx * 16, src + cidx * 8);
            cp_commit();
            cp_wait<1>();
        } else {
            cp_wait<0>();
        }
        __syncthreads();

        // ---- S = Q K^T ----
        float s[4][4];
#pragma unroll
        for (int nb = 0; nb < 4; nb++)
#pragma unroll
            for (int v = 0; v < 4; v++) s[nb][v] = 0.f;

#pragma unroll
        for (int kc = 0; kc < 4; kc++)
#pragma unroll
            for (int np = 0; np < 2; np++) {
                uint32_t kh[4], kl[4];
                ldsm4(kh, sptr(&S[st][0][np * 16 + krow_s][kc * 16 + kcol_s]));
                ldsm4(kl, sptr(&S[st][1][np * 16 + krow_s][kc * 16 + kcol_s]));
                mma_bf16(s[2*np],   qfh[kc], kh[0], kh[1]);
                mma_bf16(s[2*np],   qfh[kc], kl[0], kl[1]);
                mma_bf16(s[2*np],   qfl[kc], kh[0], kh[1]);
                mma_bf16(s[2*np+1], qfh[kc], kh[2], kh[3]);
                mma_bf16(s[2*np+1], qfh[kc], kl[2], kl[3]);
                mma_bf16(s[2*np+1], qfl[kc], kh[2], kh[3]);
            }

        // ---- scale + pos + online softmax ----
        const int j0 = i * 32;
#pragma unroll
        for (int rp = 0; rp < 2; rp++) {
            int row = r + rp * 8;
            const float* pb = pos + ((size_t)(h * LS + q0 + row)) * LS + j0 + 2 * tig;
            float rm = -1e30f;
#pragma unroll
            for (int nb = 0; nb < 4; nb++) {
                float2 pv = *(const float2*)(pb + nb * 8);
                float v0 = fmaf(s[nb][2*rp],     ATT_SCALE, pv.x);
                float v1 = fmaf(s[nb][2*rp + 1], ATT_SCALE, pv.y);
                s[nb][2*rp]     = v0;
                s[nb][2*rp + 1] = v1;
                rm = fmaxf(rm, fmaxf(v0, v1));
            }
            rm = fmaxf(rm, __shfl_xor_sync(0xffffffffu, rm, 1));
            rm = fmaxf(rm, __shfl_xor_sync(0xffffffffu, rm, 2));
            float mnew  = fmaxf(mi[rp], rm);
            float alpha = __expf(mi[rp] - mnew);
            mi[rp] = mnew;
            float rs = 0.f;
#pragma unroll
            for (int nb = 0; nb < 4; nb++) {
                float e0 = __expf(s[nb][2*rp]     - mnew);
                float e1 = __expf(s[nb][2*rp + 1] - mnew);
                s[nb][2*rp]     = e0;
                s[nb][2*rp + 1] = e1;
                rs += e0 + e1;
            }
            rs += __shfl_xor_sync(0xffffffffu, rs, 1);
            rs += __shfl_xor_sync(0xffffffffu, rs, 2);
            li[rp] = li[rp] * alpha + rs;
#pragma unroll
            for (int nd = 0; nd < 8; nd++) {
                o[nd][2*rp]     *= alpha;
                o[nd][2*rp + 1] *= alpha;
            }
        }

        // ---- P fragments (split bf16, register-only) ----
        uint32_t ph[2][4], pl[2][4];
#pragma unroll
        for (int kc = 0; kc < 2; kc++) {
            bsplit(s[2*kc][0],   s[2*kc][1],   ph[kc][0], pl[kc][0]);
            bsplit(s[2*kc][2],   s[2*kc][3],   ph[kc][1], pl[kc][1]);
            bsplit(s[2*kc+1][0], s[2*kc+1][1], ph[kc][2], pl[kc][2]);
            bsplit(s[2*kc+1][2], s[2*kc+1][3], ph[kc][3], pl[kc][3]);
        }

        // ---- O += P V ----
#pragma unroll
        for (int kc = 0; kc < 2; kc++)
#pragma unroll
            for (int np = 0; np < 4; np++) {
                uint32_t vh[4], vl[4];
                ldsm4t(vh, sptr(&S[st][2][kc * 16 + vrow_s][np * 16 + vcol_s]));
                ldsm4t(vl, sptr(&S[st][3][kc * 16 + vrow_s][np * 16 + vcol_s]));
                mma_bf16(o[2*np],   ph[kc], vh[0], vh[1]);
                mma_bf16(o[2*np],   ph[kc], vl[0], vl[1]);
                mma_bf16(o[2*np],   pl[kc], vh[0], vh[1]);
                mma_bf16(o[2*np+1], ph[kc], vh[2], vh[3]);
                mma_bf16(o[2*np+1], ph[kc], vl[2], vl[3]);
                mma_bf16(o[2*np+1], pl[kc], vh[2], vh[3]);
            }

        __syncthreads();
    }

    // ---- epilogue: normalize, write bf16 hi/lo [B,L,C] ----
    float inv0 = 1.0f / li[0];
    float inv1 = 1.0f / li[1];
#pragma unroll
    for (int nd = 0; nd < 8; nd++) {
        int d = nd * 8 + 2 * tig;
        size_t o0 = ((size_t)(b * LS + q0 + r)) * CD + h * HD + d;
        size_t o1 = ((size_t)(b * LS + q0 + r + 8)) * CD + h * HD + d;
        uint32_t hp, lp;
        bsplit(o[nd][0] * inv0, o[nd][1] * inv0, hp, lp);
        *(uint32_t*)(g_oh + o0) = hp;
        *(uint32_t*)(g_ol + o0) = lp;
        bsplit(o[nd][2] * inv1, o[nd][3] * inv1, hp, lp);
        *(uint32_t*)(g_oh + o1) = hp;
        *(uint32_t*)(g_ol + o1) = lp;
    }
}

// ---------------------------------------------------------------------------
// Output projection: out = g_o @ Wp^T + bp. A pre-split bf16, B split in-kernel.
// ---------------------------------------------------------------------------
__global__ __launch_bounds__(256) void proj_kernel(
    const float* __restrict__ Wp,
    const float* __restrict__ bp,
    float* __restrict__ out)
{
    __shared__ __nv_bfloat16 Ah[2][128][AST], Al[2][128][AST];
    __shared__ __nv_bfloat16 Bh[2][128][AST], Bl[2][128][AST];

    const int tid  = threadIdx.x;
    const int lane = tid & 31;
    const int warp = tid >> 5;
    const int gid  = lane >> 2;
    const int tig  = lane & 3;
    const int wm   = warp >> 2;
    const int wn   = warp & 3;

    const int m0 = blockIdx.y * 128;
    const int n0 = blockIdx.x * 128;
    const int lr = tid >> 1;
    const int lc = (tid & 1) << 3;

    const __nv_bfloat16* ahrow = g_oh + (size_t)(m0 + lr) * CD + lc;
    const __nv_bfloat16* alrow = g_ol + (size_t)(m0 + lr) * CD + lc;
    const float* brow = Wp + (size_t)(n0 + lr) * CD + lc;

    float c[4][4][4];
#pragma unroll
    for (int i = 0; i < 4; i++)
#pragma unroll
        for (int j = 0; j < 4; j++)
#pragma unroll
            for (int v = 0; v < 4; v++) c[i][j][v] = 0.f;

    uint4 pa_h, pa_l;
    float br[8];
    {
        pa_h = *(const uint4*)ahrow;
        pa_l = *(const uint4*)alrow;
        float4 b0 = *(const float4*)(brow);
        float4 b1 = *(const float4*)(brow + 4);
        br[0]=b0.x; br[1]=b0.y; br[2]=b0.z; br[3]=b0.w;
        br[4]=b1.x; br[5]=b1.y; br[6]=b1.z; br[7]=b1.w;
        *(uint4*)&Ah[0][lr][lc] = pa_h;
        *(uint4*)&Al[0][lr][lc] = pa_l;
        uint32_t h[4], l[4];
#pragma unroll
        for (int i = 0; i < 4; i++) bsplit(br[2*i], br[2*i+1], h[i], l[i]);
        *(uint4*)&Bh[0][lr][lc] = make_uint4(h[0], h[1], h[2], h[3]);
        *(uint4*)&Bl[0][lr][lc] = make_uint4(l[0], l[1], l[2], l[3]);
    }
    __syncthreads();

    const int arow_s = wm * 64 + (lane & 15);
    const int acol_s = (lane >> 4) * 8;
    const int brow_s = wn * 32 + ((lane >> 4) & 1) * 8 + (lane & 7);
    const int bcol_s = ((lane >> 3) & 1) * 8;

    int st = 0;
    const int NIT = CD / 16;
    for (int it = 0; it < NIT; ++it) {
        if (it + 1 < NIT) {
            int k0 = (it + 1) * 16;
            pa_h = *(const uint4*)(ahrow + k0);
            pa_l = *(const uint4*)(alrow + k0);
            float4 b0 = *(const float4*)(brow + k0);
            float4 b1 = *(const float4*)(brow + k0 + 4);
            br[0]=b0.x; br[1]=b0.y; br[2]=b0.z; br[3]=b0.w;
            br[4]=b1.x; br[5]=b1.y; br[6]=b1.z; br[7]=b1.w;
        }

        uint32_t fah[4][4], fal[4][4], fbh[2][4], fbl[2][4];
#pragma unroll
        for (int ma = 0; ma < 4; ma++) {
            ldsm4(fah[ma], sptr(&Ah[st][arow_s + ma * 16][acol_s]));
            ldsm4(fal[ma], sptr(&Al[st][arow_s + ma * 16][acol_s]));
        }
#pragma unroll
        for (int np = 0; np < 2; np++) {
            ldsm4(fbh[np], sptr(&Bh[st][brow_s + np * 16][bcol_s]));
            ldsm4(fbl[np], sptr(&Bl[st][brow_s + np * 16][bcol_s]));
        }
#pragma unroll
        for (int ma = 0; ma < 4; ma++)
#pragma unroll
            for (int nb = 0; nb < 4; nb++) {
                const int np = nb >> 1, sel = (nb & 1) * 2;
                mma_bf16(c[ma][nb], fah[ma], fbh[np][sel], fbh[np][sel + 1]);
                mma_bf16(c[ma][nb], fah[ma], fbl[np][sel], fbl[np][sel + 1]);
                mma_bf16(c[ma][nb], fal[ma], fbh[np][sel], fbh[np][sel + 1]);
            }

        if (it + 1 < NIT) {
            *(uint4*)&Ah[st ^ 1][lr][lc] = pa_h;
            *(uint4*)&Al[st ^ 1][lr][lc] = pa_l;
            uint32_t h[4], l[4];
#pragma unroll
            for (int i = 0; i < 4; i++) bsplit(br[2*i], br[2*i+1], h[i], l[i]);
            *(uint4*)&Bh[st ^ 1][lr][lc] = make_uint4(h[0], h[1], h[2], h[3]);
            *(uint4*)&Bl[st ^ 1][lr][lc] = make_uint4(l[0], l[1], l[2], l[3]);
            __syncthreads();
            st ^= 1;
        }
    }

#pragma unroll
    for (int ma = 0; ma < 4; ma++) {
        int row0 = m0 + wm * 64 + ma * 16 + gid;
        int row1 = row0 + 8;
#pragma unroll
        for (int nb = 0; nb < 4; nb++) {
            int n = n0 + wn * 32 + nb * 8 + 2 * tig;
            float2 bias = *(const float2*)(bp + n);
            *(float2*)(out + (size_t)row0 * CD + n) =
                make_float2(c[ma][nb][0] + bias.x, c[ma][nb][1] + bias.y);
            *(float2*)(out + (size_t)row1 * CD + n) =
                make_float2(c[ma][nb][2] + bias.x, c[ma][nb][3] + bias.y);
        }
    }
}

// ---------------------------------------------------------------------------
extern "C" void kernel_launch(void* const* d_in, const int* in_sizes, int n_in,
                              void* d_out, int out_size)
{
    const float* x    = (const float*)d_in[0];
    const float* qape = (const float*)d_in[1];
    const float* kape = (const float*)d_in[2];
    const float* pos  = (const float*)d_in[3];
    const float* Wq   = (const float*)d_in[4];
    const float* Wk   = (const float*)d_in[5];
    const float* Wv   = (const float*)d_in[6];
    const float* Wp   = (const float*)d_in[7];
    const float* bp   = (const float*)d_in[8];
    float* out = (float*)d_out;

    dim3 gemm_grid(CD / 128, ML / 128, 3);
    qkv_kernel<<<gemm_grid, 256>>>(x, qape, kape, Wq, Wk, Wv);

    dim3 attn_grid(LS / 64, BATCH * NH);
    attn_kernel<<<attn_grid, 128>>>(pos);

    dim3 proj_grid(CD / 128, ML / 128, 1);
    proj_kernel<<<proj_grid, 256>>>(Wp, bp, out);
}

// round 8
// speedup vs baseline: 1.1882x; 1.1852x over previous
#include <cuda_runtime.h>
#include <cuda_bf16.h>
#include <cstdint>

#define NH 12
#define HD 64
#define CD 768
#define LS 1024
#define BATCH 4
#define ML (BATCH*LS)
#define ATT_SCALE 0.125f

// Pre-split bf16 scratch (hi+lo pairs).
__device__ __align__(16) __nv_bfloat16 g_xqh[ML*CD], g_xql[ML*CD];  // x+q_ape [ML,CD]
__device__ __align__(16) __nv_bfloat16 g_xkh[ML*CD], g_xkl[ML*CD];  // x+k_ape
__device__ __align__(16) __nv_bfloat16 g_xvh[ML*CD], g_xvl[ML*CD];  // x
__device__ __align__(16) __nv_bfloat16 g_wqh[CD*CD], g_wql[CD*CD];
__device__ __align__(16) __nv_bfloat16 g_wkh[CD*CD], g_wkl[CD*CD];
__device__ __align__(16) __nv_bfloat16 g_wvh[CD*CD], g_wvl[CD*CD];
__device__ __align__(16) __nv_bfloat16 g_wph[CD*CD], g_wpl[CD*CD];
__device__ __align__(16) __nv_bfloat16 g_qh[ML*CD], g_ql[ML*CD];    // [B,H,L,D]
__device__ __align__(16) __nv_bfloat16 g_kh[ML*CD], g_kl[ML*CD];
__device__ __align__(16) __nv_bfloat16 g_vh[ML*CD], g_vl[ML*CD];
__device__ __align__(16) __nv_bfloat16 g_oh[ML*CD], g_ol[ML*CD];    // [B,L,C]

// ---------------- helpers ----------------
__device__ __forceinline__ uint32_t sptr(const void* p) {
    return (uint32_t)__cvta_generic_to_shared(p);
}
__device__ __forceinline__ void bsplit(float x, float y, uint32_t& hp, uint32_t& lp) {
    __nv_bfloat16 hx = __float2bfloat16_rn(x);
    __nv_bfloat16 hy = __float2bfloat16_rn(y);
    float rx = x - __bfloat162float(hx);
    float ry = y - __bfloat162float(hy);
    __nv_bfloat16 lx = __float2bfloat16_rn(rx);
    __nv_bfloat16 ly = __float2bfloat16_rn(ry);
    hp = (uint32_t)__bfloat16_as_ushort(hx) | ((uint32_t)__bfloat16_as_ushort(hy) << 16);
    lp = (uint32_t)__bfloat16_as_ushort(lx) | ((uint32_t)__bfloat16_as_ushort(ly) << 16);
}
__device__ __forceinline__ void ldsm4(uint32_t* r, uint32_t a) {
    asm volatile("ldmatrix.sync.aligned.m8n8.x4.shared.b16 {%0,%1,%2,%3},[%4];\n"
                 : "=r"(r[0]), "=r"(r[1]), "=r"(r[2]), "=r"(r[3]) : "r"(a));
}
__device__ __forceinline__ void ldsm4t(uint32_t* r, uint32_t a) {
    asm volatile("ldmatrix.sync.aligned.m8n8.x4.trans.shared.b16 {%0,%1,%2,%3},[%4];\n"
                 : "=r"(r[0]), "=r"(r[1]), "=r"(r[2]), "=r"(r[3]) : "r"(a));
}
__device__ __forceinline__ void mma_bf16(float* c, const uint32_t* a, uint32_t b0, uint32_t b1) {
    asm volatile(
        "mma.sync.aligned.m16n8k16.row.col.f32.bf16.bf16.f32 "
        "{%0,%1,%2,%3},{%4,%5,%6,%7},{%8,%9},{%0,%1,%2,%3};\n"
        : "+f"(c[0]), "+f"(c[1]), "+f"(c[2]), "+f"(c[3])
        : "r"(a[0]), "r"(a[1]), "r"(a[2]), "r"(a[3]), "r"(b0), "r"(b1));
}
__device__ __forceinline__ void cpa16(uint32_t dst, const void* src) {
    asm volatile("cp.async.cg.shared.global [%0], [%1], 16;\n" :: "r"(dst), "l"(src));
}
__device__ __forceinline__ void cp_commit() { asm volatile("cp.async.commit_group;\n"); }
template<int N> __device__ __forceinline__ void cp_wait() {
    asm volatile("cp.async.wait_group %0;\n" :: "n"(N));
}

// ---------------------------------------------------------------------------
// Prep: split x(+ape) variants into bf16 hi/lo. 4 elements/thread.
// ---------------------------------------------------------------------------
__global__ __launch_bounds__(256) void prep_x(
    const float* __restrict__ x,
    const float* __restrict__ qape,
    const float* __restrict__ kape)
{
    const int idx = (blockIdx.x * 256 + threadIdx.x) * 4;
    const int m = idx / CD;
    const int c = idx - m * CD;
    const int l = m & (LS - 1);

    float4 xv = *(const float4*)(x + idx);
    float4 qa = *(const float4*)(qape + (size_t)l * CD + c);
    float4 ka = *(const float4*)(kape + (size_t)l * CD + c);

    uint32_t h0, l0, h1, l1;
    bsplit(xv.x + qa.x, xv.y + qa.y, h0, l0);
    bsplit(xv.z + qa.z, xv.w + qa.w, h1, l1);
    *(uint2*)(g_xqh + idx) = make_uint2(h0, h1);
    *(uint2*)(g_xql + idx) = make_uint2(l0, l1);

    bsplit(xv.x + ka.x, xv.y + ka.y, h0, l0);
    bsplit(xv.z + ka.z, xv.w + ka.w, h1, l1);
    *(uint2*)(g_xkh + idx) = make_uint2(h0, h1);
    *(uint2*)(g_xkl + idx) = make_uint2(l0, l1);

    bsplit(xv.x, xv.y, h0, l0);
    bsplit(xv.z, xv.w, h1, l1);
    *(uint2*)(g_xvh + idx) = make_uint2(h0, h1);
    *(uint2*)(g_xvl + idx) = make_uint2(l0, l1);
}

__global__ __launch_bounds__(256) void prep_w(
    const float* __restrict__ Wq, const float* __restrict__ Wk,
    const float* __restrict__ Wv, const float* __restrict__ Wp)
{
    const int mat = blockIdx.y;
    const float* W = (mat == 0) ? Wq : (mat == 1) ? Wk : (mat == 2) ? Wv : Wp;
    __nv_bfloat16* wh = (mat == 0) ? g_wqh : (mat == 1) ? g_wkh : (mat == 2) ? g_wvh : g_wph;
    __nv_bfloat16* wl = (mat == 0) ? g_wql : (mat == 1) ? g_wkl : (mat == 2) ? g_wvl : g_wpl;

    const int idx = (blockIdx.x * 256 + threadIdx.x) * 4;
    float4 v = *(const float4*)(W + idx);
    uint32_t h0, l0, h1, l1;
    bsplit(v.x, v.y, h0, l0);
    bsplit(v.z, v.w, h1, l1);
    *(uint2*)(wh + idx) = make_uint2(h0, h1);
    *(uint2*)(wl + idx) = make_uint2(l0, l1);
}

// ---------------------------------------------------------------------------
// QKV GEMM: C[m,n] = sum_k A[m,k]*W[n,k], pre-split bf16, cp.async 2-stage.
// Block 128x128, BK=16, 256 thr (8 warps 2x4), warp 64x32, bf16x3 MMA.
// ---------------------------------------------------------------------------
#define AST 24

__global__ __launch_bounds__(256, 2) void qkv_gemm()
{
    __shared__ __nv_bfloat16 Ah[2][128][AST], Al[2][128][AST];
    __shared__ __nv_bfloat16 Bh[2][128][AST], Bl[2][128][AST];

    const int which = blockIdx.z;
    const __nv_bfloat16* pAh = (which == 0) ? g_xqh : (which == 1) ? g_xkh : g_xvh;
    const __nv_bfloat16* pAl = (which == 0) ? g_xql : (which == 1) ? g_xkl : g_xvl;
    const __nv_bfloat16* pBh = (which == 0) ? g_wqh : (which == 1) ? g_wkh : g_wvh;
    const __nv_bfloat16* pBl = (which == 0) ? g_wql : (which == 1) ? g_wkl : g_wvl;
    __nv_bfloat16* outh = (which == 0) ? g_qh : (which == 1) ? g_kh : g_vh;
    __nv_bfloat16* outl = (which == 0) ? g_ql : (which == 1) ? g_kl : g_vl;

    const int tid  = threadIdx.x;
    const int lane = tid & 31;
    const int warp = tid >> 5;
    const int gid  = lane >> 2;
    const int tig  = lane & 3;
    const int wm   = warp >> 2;
    const int wn   = warp & 3;

    const int m0 = blockIdx.y * 128;
    const int n0 = blockIdx.x * 128;
    const int lr = tid >> 1;
    const int lc = (tid & 1) << 3;

    const __nv_bfloat16* ah = pAh + (size_t)(m0 + lr) * CD + lc;
    const __nv_bfloat16* al = pAl + (size_t)(m0 + lr) * CD + lc;
    const __nv_bfloat16* bh = pBh + (size_t)(n0 + lr) * CD + lc;
    const __nv_bfloat16* bl = pBl + (size_t)(n0 + lr) * CD + lc;

    float c[4][4][4];
#pragma unroll
    for (int i = 0; i < 4; i++)
#pragma unroll
        for (int j = 0; j < 4; j++)
#pragma unroll
            for (int v = 0; v < 4; v++) c[i][j][v] = 0.f;

    // stage 0 loads
    cpa16(sptr(&Ah[0][lr][lc]), ah);
    cpa16(sptr(&Al[0][lr][lc]), al);
    cpa16(sptr(&Bh[0][lr][lc]), bh);
    cpa16(sptr(&Bl[0][lr][lc]), bl);
    cp_commit();

    const int arow_s = wm * 64 + (lane & 15);
    const int acol_s = (lane >> 4) * 8;
    const int brow_s = wn * 32 + ((lane >> 4) & 1) * 8 + (lane & 7);
    const int bcol_s = ((lane >> 3) & 1) * 8;

    const int NIT = CD / 16;
    for (int it = 0; it < NIT; ++it) {
        const int st = it & 1;
        if (it + 1 < NIT) {
            const int k0 = (it + 1) * 16;
            cpa16(sptr(&Ah[st ^ 1][lr][lc]), ah + k0);
            cpa16(sptr(&Al[st ^ 1][lr][lc]), al + k0);
            cpa16(sptr(&Bh[st ^ 1][lr][lc]), bh + k0);
            cpa16(sptr(&Bl[st ^ 1][lr][lc]), bl + k0);
            cp_commit();
            cp_wait<1>();
        } else {
            cp_wait<0>();
        }
        __syncthreads();

        uint32_t fah[4][4], fal[4][4], fbh[2][4], fbl[2][4];
#pragma unroll
        for (int ma = 0; ma < 4; ma++) {
            ldsm4(fah[ma], sptr(&Ah[st][arow_s + ma * 16][acol_s]));
            ldsm4(fal[ma], sptr(&Al[st][arow_s + ma * 16][acol_s]));
        }
#pragma unroll
        for (int np = 0; np < 2; np++) {
            ldsm4(fbh[np], sptr(&Bh[st][brow_s + np * 16][bcol_s]));
            ldsm4(fbl[np], sptr(&Bl[st][brow_s + np * 16][bcol_s]));
        }
#pragma unroll
        for (int ma = 0; ma < 4; ma++)
#pragma unroll
            for (int nb = 0; nb < 4; nb++) {
                const int np = nb >> 1, sel = (nb & 1) * 2;
                mma_bf16(c[ma][nb], fah[ma], fbh[np][sel], fbh[np][sel + 1]);
                mma_bf16(c[ma][nb], fah[ma], fbl[np][sel], fbl[np][sel + 1]);
                mma_bf16(c[ma][nb], fal[ma], fbh[np][sel], fbh[np][sel + 1]);
            }
        __syncthreads();
    }

    // epilogue -> [B,H,L,D] bf16 hi/lo
#pragma unroll
    for (int ma = 0; ma < 4; ma++) {
        int row0 = m0 + wm * 64 + ma * 16 + gid;
        int row1 = row0 + 8;
        int b0i = row0 >> 10, l0 = row0 & (LS - 1);
        int b1i = row1 >> 10, l1 = row1 & (LS - 1);
#pragma unroll
        for (int nb = 0; nb < 4; nb++) {
            int n = n0 + wn * 32 + nb * 8 + 2 * tig;
            int h = n >> 6, d = n & 63;
            size_t o0 = ((size_t)((b0i * NH + h) * LS + l0)) * HD + d;
            size_t o1 = ((size_t)((b1i * NH + h) * LS + l1)) * HD + d;
            uint32_t hp, lp;
            bsplit(c[ma][nb][0], c[ma][nb][1], hp, lp);
            *(uint32_t*)(outh + o0) = hp;
            *(uint32_t*)(outl + o0) = lp;
            bsplit(c[ma][nb][2], c[ma][nb][3], hp, lp);
            *(uint32_t*)(outh + o1) = hp;
            *(uint32_t*)(outl + o1) = lp;
        }
    }
}

// ---------------------------------------------------------------------------
// Attention (unchanged from round 7): per (b,h), 64-q block, 4 warps,
// 32-key tiles, pre-split operands via cp.async, bf16x3 MMAs.
// ---------------------------------------------------------------------------
#define KST 72

__global__ __launch_bounds__(128) void attn_kernel(const float* __restrict__ pos)
{
    __shared__ __nv_bfloat16 S[2][4][32][KST];

    const int tid  = threadIdx.x;
    const int lane = tid & 31;
    const int warp = tid >> 5;
    const int gid  = lane >> 2;
    const int tig  = lane & 3;

    const int bh = blockIdx.y;
    const int b  = bh / NH;
    const int h  = bh - b * NH;
    const int q0 = blockIdx.x * 64;

    const size_t base = (size_t)bh * LS * HD;

    __nv_bfloat16* Qh = &S[0][0][0][0];
    __nv_bfloat16* Ql = Qh + 64 * KST;
    {
        const __nv_bfloat16* src = ((warp & 2) ? g_ql : g_qh) +
            base + (size_t)(q0 + (warp & 1) * 32 + lane) * HD;
        __nv_bfloat16* dst = ((warp & 2) ? Ql : Qh) + ((warp & 1) * 32 + lane) * KST;
        uint32_t d0 = sptr(dst);
#pragma unroll
        for (int cidx = 0; cidx < 8; cidx++) cpa16(d0 + cidx * 16, src + cidx * 8);
    }
    cp_commit();
    cp_wait<0>();
    __syncthreads();

    uint32_t qfh[4][4], qfl[4][4];
    {
        const int qrow = warp * 16 + (lane & 15);
        const int qc   = (lane >> 4) * 8;
#pragma unroll
        for (int kc = 0; kc < 4; kc++) {
            ldsm4(qfh[kc], sptr(Qh + qrow * KST + kc * 16 + qc));
            ldsm4(qfl[kc], sptr(Ql + qrow * KST + kc * 16 + qc));
        }
    }
    __syncthreads();

    const __nv_bfloat16* kvsrc =
        ((warp == 0) ? g_kh : (warp == 1) ? g_kl : (warp == 2) ? g_vh : g_vl) + base;

    {
        const __nv_bfloat16* src = kvsrc + (size_t)lane * HD;
        uint32_t d0 = sptr(&S[0][warp][lane][0]);
#pragma unroll
        for (int cidx = 0; cidx < 8; cidx++) cpa16(d0 + cidx * 16, src + cidx * 8);
    }
    cp_commit();

    const int r = warp * 16 + gid;
    float o[8][4];
#pragma unroll
    for (int nd = 0; nd < 8; nd++)
#pragma unroll
        for (int v = 0; v < 4; v++) o[nd][v] = 0.f;
    float mi[2] = {-1e30f, -1e30f};
    float li[2] = {0.f, 0.f};

    const int krow_s = ((lane >> 4) & 1) * 8 + (lane & 7);
    const int kcol_s = ((lane >> 3) & 1) * 8;
    const int vrow_s = ((lane >> 3) & 1) * 8 + (lane & 7);
    const int vcol_s = ((lane >> 4) & 1) * 8;

    const int NJ = LS / 32;
    for (int i = 0; i < NJ; i++) {
        const int st = i & 1;
        if (i + 1 < NJ) {
            const __nv_bfloat16* src = kvsrc + (size_t)((i + 1) * 32 + lane) * HD;
            uint32_t d0 = sptr(&S[st ^ 1][warp][lane][0]);
#pragma unroll
            for (int cidx = 0; cidx < 8; cidx++) cpa16(d0 + cidx * 16, src + cidx * 8);
            cp_commit();
            cp_wait<1>();
        } else {
            cp_wait<0>();
        }
        __syncthreads();

        float s[4][4];
#pragma unroll
        for (int nb = 0; nb < 4; nb++)
#pragma unroll
            for (int v = 0; v < 4; v++) s[nb][v] = 0.f;

#pragma unroll
        for (int kc = 0; kc < 4; kc++)
#pragma unroll
            for (int np = 0; np < 2; np++) {
                uint32_t kh[4], kl[4];
                ldsm4(kh, sptr(&S[st][0][np * 16 + krow_s][kc * 16 + kcol_s]));
                ldsm4(kl, sptr(&S[st][1][np * 16 + krow_s][kc * 16 + kcol_s]));
                mma_bf16(s[2*np],   qfh[kc], kh[0], kh[1]);
                mma_bf16(s[2*np],   qfh[kc], kl[0], kl[1]);
                mma_bf16(s[2*np],   qfl[kc], kh[0], kh[1]);
                mma_bf16(s[2*np+1], qfh[kc], kh[2], kh[3]);
                mma_bf16(s[2*np+1], qfh[kc], kl[2], kl[3]);
                mma_bf16(s[2*np+1], qfl[kc], kh[2], kh[3]);
            }

        const int j0 = i * 32;
#pragma unroll
        for (int rp = 0; rp < 2; rp++) {
            int row = r + rp * 8;
            const float* pb = pos + ((size_t)(h * LS + q0 + row)) * LS + j0 + 2 * tig;
            float rm = -1e30f;
#pragma unroll
            for (int nb = 0; nb < 4; nb++) {
                float2 pv = *(const float2*)(pb + nb * 8);
                float v0 = fmaf(s[nb][2*rp],     ATT_SCALE, pv.x);
                float v1 = fmaf(s[nb][2*rp + 1], ATT_SCALE, pv.y);
                s[nb][2*rp]     = v0;
                s[nb][2*rp + 1] = v1;
                rm = fmaxf(rm, fmaxf(v0, v1));
            }
            rm = fmaxf(rm, __shfl_xor_sync(0xffffffffu, rm, 1));
            rm = fmaxf(rm, __shfl_xor_sync(0xffffffffu, rm, 2));
            float mnew  = fmaxf(mi[rp], rm);
            float alpha = __expf(mi[rp] - mnew);
            mi[rp] = mnew;
            float rs = 0.f;
#pragma unroll
            for (int nb = 0; nb < 4; nb++) {
                float e0 = __expf(s[nb][2*rp]     - mnew);
                float e1 = __expf(s[nb][2*rp + 1] - mnew);
                s[nb][2*rp]     = e0;
                s[nb][2*rp + 1] = e1;
                rs += e0 + e1;
            }
            rs += __shfl_xor_sync(0xffffffffu, rs, 1);
            rs += __shfl_xor_sync(0xffffffffu, rs, 2);
            li[rp] = li[rp] * alpha + rs;
#pragma unroll
            for (int nd = 0; nd < 8; nd++) {
                o[nd][2*rp]     *= alpha;
                o[nd][2*rp + 1] *= alpha;
            }
        }

        uint32_t ph[2][4], pl[2][4];
#pragma unroll
        for (int kc = 0; kc < 2; kc++) {
            bsplit(s[2*kc][0],   s[2*kc][1],   ph[kc][0], pl[kc][0]);
            bsplit(s[2*kc][2],   s[2*kc][3],   ph[kc][1], pl[kc][1]);
            bsplit(s[2*kc+1][0], s[2*kc+1][1], ph[kc][2], pl[kc][2]);
            bsplit(s[2*kc+1][2], s[2*kc+1][3], ph[kc][3], pl[kc][3]);
        }

#pragma unroll
        for (int kc = 0; kc < 2; kc++)
#pragma unroll
            for (int np = 0; np < 4; np++) {
                uint32_t vh[4], vl[4];
                ldsm4t(vh, sptr(&S[st][2][kc * 16 + vrow_s][np * 16 + vcol_s]));
                ldsm4t(vl, sptr(&S[st][3][kc * 16 + vrow_s][np * 16 + vcol_s]));
                mma_bf16(o[2*np],   ph[kc], vh[0], vh[1]);
                mma_bf16(o[2*np],   ph[kc], vl[0], vl[1]);
                mma_bf16(o[2*np],   pl[kc], vh[0], vh[1]);
                mma_bf16(o[2*np+1], ph[kc], vh[2], vh[3]);
                mma_bf16(o[2*np+1], ph[kc], vl[2], vl[3]);
                mma_bf16(o[2*np+1], pl[kc], vh[2], vh[3]);
            }

        __syncthreads();
    }

    float inv0 = 1.0f / li[0];
    float inv1 = 1.0f / li[1];
#pragma unroll
    for (int nd = 0; nd < 8; nd++) {
        int d = nd * 8 + 2 * tig;
        size_t o0 = ((size_t)(b * LS + q0 + r)) * CD + h * HD + d;
        size_t o1 = ((size_t)(b * LS + q0 + r + 8)) * CD + h * HD + d;
        uint32_t hp, lp;
        bsplit(o[nd][0] * inv0, o[nd][1] * inv0, hp, lp);
        *(uint32_t*)(g_oh + o0) = hp;
        *(uint32_t*)(g_ol + o0) = lp;
        bsplit(o[nd][2] * inv1, o[nd][3] * inv1, hp, lp);
        *(uint32_t*)(g_oh + o1) = hp;
        *(uint32_t*)(g_ol + o1) = lp;
    }
}

// ---------------------------------------------------------------------------
// Output projection: out = g_o @ Wp^T + bp (all operands pre-split bf16).
// ---------------------------------------------------------------------------
__global__ __launch_bounds__(256, 2) void proj_gemm(
    const float* __restrict__ bp,
    float* __restrict__ out)
{
    __shared__ __nv_bfloat16 Ah[2][128][AST], Al[2][128][AST];
    __shared__ __nv_bfloat16 Bh[2][128][AST], Bl[2][128][AST];

    const int tid  = threadIdx.x;
    const int lane = tid & 31;
    const int warp = tid >> 5;
    const int gid  = lane >> 2;
    const int tig  = lane & 3;
    const int wm   = warp >> 2;
    const int wn   = warp & 3;

    const int m0 = blockIdx.y * 128;
    const int n0 = blockIdx.x * 128;
    const int lr = tid >> 1;
    const int lc = (tid & 1) << 3;

    const __nv_bfloat16* ah = g_oh  + (size_t)(m0 + lr) * CD + lc;
    const __nv_bfloat16* al = g_ol  + (size_t)(m0 + lr) * CD + lc;
    const __nv_bfloat16* bh = g_wph + (size_t)(n0 + lr) * CD + lc;
    const __nv_bfloat16* bl = g_wpl + (size_t)(n0 + lr) * CD + lc;

    float c[4][4][4];
#pragma unroll
    for (int i = 0; i < 4; i++)
#pragma unroll
        for (int j = 0; j < 4; j++)
#pragma unroll
            for (int v = 0; v < 4; v++) c[i][j][v] = 0.f;

    cpa16(sptr(&Ah[0][lr][lc]), ah);
    cpa16(sptr(&Al[0][lr][lc]), al);
    cpa16(sptr(&Bh[0][lr][lc]), bh);
    cpa16(sptr(&Bl[0][lr][lc]), bl);
    cp_commit();

    const int arow_s = wm * 64 + (lane & 15);
    const int acol_s = (lane >> 4) * 8;
    const int brow_s = wn * 32 + ((lane >> 4) & 1) * 8 + (lane & 7);
    const int bcol_s = ((lane >> 3) & 1) * 8;

    const int NIT = CD / 16;
    for (int it = 0; it < NIT; ++it) {
        const int st = it & 1;
        if (it + 1 < NIT) {
            const int k0 = (it + 1) * 16;
            cpa16(sptr(&Ah[st ^ 1][lr][lc]), ah + k0);
            cpa16(sptr(&Al[st ^ 1][lr][lc]), al + k0);
            cpa16(sptr(&Bh[st ^ 1][lr][lc]), bh + k0);
            cpa16(sptr(&Bl[st ^ 1][lr][lc]), bl + k0);
            cp_commit();
            cp_wait<1>();
        } else {
            cp_wait<0>();
        }
        __syncthreads();

        uint32_t fah[4][4], fal[4][4], fbh[2][4], fbl[2][4];
#pragma unroll
        for (int ma = 0; ma < 4; ma++) {
            ldsm4(fah[ma], sptr(&Ah[st][arow_s + ma * 16][acol_s]));
            ldsm4(fal[ma], sptr(&Al[st][arow_s + ma * 16][acol_s]));
        }
#pragma unroll
        for (int np = 0; np < 2; np++) {
            ldsm4(fbh[np], sptr(&Bh[st][brow_s + np * 16][bcol_s]));
            ldsm4(fbl[np], sptr(&Bl[st][brow_s + np * 16][bcol_s]));
        }
#pragma unroll
        for (int ma = 0; ma < 4; ma++)
#pragma unroll
            for (int nb = 0; nb < 4; nb++) {
                const int np = nb >> 1, sel = (nb & 1) * 2;
                mma_bf16(c[ma][nb], fah[ma], fbh[np][sel], fbh[np][sel + 1]);
                mma_bf16(c[ma][nb], fah[ma], fbl[np][sel], fbl[np][sel + 1]);
                mma_bf16(c[ma][nb], fal[ma], fbh[np][sel], fbh[np][sel + 1]);
            }
        __syncthreads();
    }

#pragma unroll
    for (int ma = 0; ma < 4; ma++) {
        int row0 = m0 + wm * 64 + ma * 16 + gid;
        int row1 = row0 + 8;
#pragma unroll
        for (int nb = 0; nb < 4; nb++) {
            int n = n0 + wn * 32 + nb * 8 + 2 * tig;
            float2 bias = *(const float2*)(bp + n);
            *(float2*)(out + (size_t)row0 * CD + n) =
                make_float2(c[ma][nb][0] + bias.x, c[ma][nb][1] + bias.y);
            *(float2*)(out + (size_t)row1 * CD + n) =
                make_float2(c[ma][nb][2] + bias.x, c[ma][nb][3] + bias.y);
        }
    }
}

// ---------------------------------------------------------------------------
extern "C" void kernel_launch(void* const* d_in, const int* in_sizes, int n_in,
                              void* d_out, int out_size)
{
    const float* x    = (const float*)d_in[0];
    const float* qape = (const float*)d_in[1];
    const float* kape = (const float*)d_in[2];
    const float* pos  = (const float*)d_in[3];
    const float* Wq   = (const float*)d_in[4];
    const float* Wk   = (const float*)d_in[5];
    const float* Wv   = (const float*)d_in[6];
    const float* Wp   = (const float*)d_in[7];
    const float* bp   = (const float*)d_in[8];
    float* out = (float*)d_out;

    prep_x<<<ML * CD / (256 * 4), 256>>>(x, qape, kape);
    dim3 wgrid(CD * CD / (256 * 4), 4);
    prep_w<<<wgrid, 256>>>(Wq, Wk, Wv, Wp);

    dim3 gemm_grid(CD / 128, ML / 128, 3);
    qkv_gemm<<<gemm_grid, 256>>>();

    dim3 attn_grid(LS / 64, BATCH * NH);
    attn_kernel<<<attn_grid, 128>>>(pos);

    dim3 proj_grid(CD / 128, ML / 128, 1);
    proj_gemm<<<proj_grid, 256>>>(bp, out);
}